// round 16
// baseline (speedup 1.0000x reference)
#include <cuda_runtime.h>
#include <cuda_bf16.h>
#include <cuda_fp16.h>
#include <cstdint>

#define NN   50000
#define EE   800000
#define HIDC 256
#define OUTC 128
#define NB_S 98   // ceil(NN/512)

// ---------------- scratch (static device globals; no allocation) ----------------
__device__ int   d_is64;
__device__ int   d_deg[NN];
__device__ float d_dinv[NN];
__device__ int   d_rowptr[NN + 1];
__device__ int   d_cursor[NN];
__device__ int   d_bsum[NB_S];
__device__ int2  d_csr[EE];                    // (src, w as float bits)
__device__ __half d_h0f16[(size_t)NN * HIDC];  // x @ W1 (fp16)
__device__ __half d_hf16 [(size_t)NN * HIDC];  // relu(Agg(h0) + b1) (fp16)
__device__ __half d_gf16 [(size_t)NN * HIDC];  // Agg(h) (fp16)
__device__ __half d_W1Tf16[HIDC * HIDC];       // W1^T  [n][k] fp16
__device__ __half d_BcTf16[HIDC * HIDC];       // [Wmu|Wls]^T [n][k] fp16
__device__ float d_bcat[256];                  // [b_mu | b_ls]

// ---------------- helpers ----------------
__device__ __forceinline__ uint32_t smem_u32(const void* p) {
    uint32_t a;
    asm("{ .reg .u64 t; cvta.to.shared.u64 t, %1; cvt.u32.u64 %0, t; }" : "=r"(a) : "l"(p));
    return a;
}
__device__ __forceinline__ void ldmat_x4(uint32_t& r0, uint32_t& r1, uint32_t& r2,
                                         uint32_t& r3, uint32_t addr) {
    asm volatile("ldmatrix.sync.aligned.m8n8.x4.shared.b16 {%0,%1,%2,%3}, [%4];"
                 : "=r"(r0), "=r"(r1), "=r"(r2), "=r"(r3) : "r"(addr));
}
__device__ __forceinline__ void mma_f16(float* c, const uint32_t* a,
                                        uint32_t b0, uint32_t b1) {
    asm volatile("mma.sync.aligned.m16n8k16.row.col.f32.f16.f16.f32 "
                 "{%0,%1,%2,%3}, {%4,%5,%6,%7}, {%8,%9}, {%0,%1,%2,%3};"
                 : "+f"(c[0]), "+f"(c[1]), "+f"(c[2]), "+f"(c[3])
                 : "r"(a[0]), "r"(a[1]), "r"(a[2]), "r"(a[3]), "r"(b0), "r"(b1));
}
__device__ __forceinline__ uint32_t sw_addr(uint32_t base, int row, int kc) {
    return base + row * 128 + ((kc ^ (row & 7)) << 4);
}
// load 8 consecutive edge indices with wide loads (base must be multiple of 8)
__device__ __forceinline__ void load_idx8(const void* ei, size_t pos, int* out) {
    if (d_is64) {
        const longlong2* p = (const longlong2*)((const long long*)ei + pos);
#pragma unroll
        for (int i = 0; i < 4; i++) {
            longlong2 v = p[i];
            out[2 * i]     = (int)v.x;
            out[2 * i + 1] = (int)v.y;
        }
    } else {
        const int4* p = (const int4*)((const int*)ei + pos);
#pragma unroll
        for (int i = 0; i < 2; i++) {
            int4 v = p[i];
            out[4 * i] = v.x; out[4 * i + 1] = v.y;
            out[4 * i + 2] = v.z; out[4 * i + 3] = v.w;
        }
    }
}
__device__ __forceinline__ void fma8(float* acc, uint4 v, float w) {
    __half2* h = (__half2*)&v;
#pragma unroll
    for (int i = 0; i < 4; i++) {
        float2 f = __half22float2(h[i]);
        acc[2 * i]     += w * f.x;
        acc[2 * i + 1] += w * f.y;
    }
}

// ---------------- setup kernels ----------------
__global__ void k_detect(const unsigned long long* __restrict__ ei) {
    if (threadIdx.x == 0) {
        int is64 = 1;
        for (int j = 0; j < 128; j++)
            if (ei[j] >= (1ull << 32)) { is64 = 0; break; }
        d_is64 = is64;
    }
}
// 8 edges per thread (EE % 8 == 0)
__global__ void k_count(const void* __restrict__ ei) {
    int base = (blockIdx.x * 256 + threadIdx.x) * 8;
    if (base < EE) {
        int dst[8];
        load_idx8(ei, (size_t)EE + base, dst);
#pragma unroll
        for (int j = 0; j < 8; j++) atomicAdd(&d_deg[dst[j]], 1);
    }
}
// ---- 2-phase parallel scan (edge-only counts; self-loop via +1 in dinv)
__global__ __launch_bounds__(512) void k_scan1() {
    __shared__ int sw[16];
    int b = blockIdx.x, tid = threadIdx.x;
    int i = b * 512 + tid;
    int lane = tid & 31, wid = tid >> 5;
    int deg = (i < NN) ? d_deg[i] : 0;
    if (i < NN) d_dinv[i] = rsqrtf((float)(deg + 1));
    int x = deg;
#pragma unroll
    for (int d = 1; d < 32; d <<= 1) {
        int t = __shfl_up_sync(0xffffffffu, x, d);
        if (lane >= d) x += t;
    }
    if (lane == 31) sw[wid] = x;
    __syncthreads();
    if (wid == 0 && lane < 16) {
        int y = sw[lane];
#pragma unroll
        for (int d = 1; d < 16; d <<= 1) {
            int t = __shfl_up_sync(0xffffu, y, d);
            if (lane >= d) y += t;
        }
        sw[lane] = y;
    }
    __syncthreads();
    int incl = x + ((wid > 0) ? sw[wid - 1] : 0);
    if (i < NN) d_rowptr[i + 1] = incl;
    if (tid == 511) d_bsum[b] = incl;
}
// scan3 with inlined block-offset computation (replaces old scan2 kernel)
__global__ __launch_bounds__(512) void k_scan3() {
    __shared__ int red[4];
    int tid = threadIdx.x, b = blockIdx.x;
    int v = (tid < NB_S && tid < b) ? d_bsum[tid] : 0;
    if (tid < 128) {
        int lane = tid & 31, w = tid >> 5;
#pragma unroll
        for (int d = 16; d > 0; d >>= 1) v += __shfl_down_sync(0xffffffffu, v, d);
        if (lane == 0) red[w] = v;
    }
    __syncthreads();
    int offset = red[0] + red[1] + red[2] + red[3];
    int i = b * 512 + tid;
    if (i < NN) {
        int r = d_rowptr[i + 1] + offset;
        d_rowptr[i + 1] = r;
        d_cursor[i]     = r - d_deg[i];
    }
    if (i == 0) d_rowptr[0] = 0;
}
// 8 edges per thread
__global__ void k_fill(const void* __restrict__ ei) {
    int base = (blockIdx.x * 256 + threadIdx.x) * 8;
    if (base < EE) {
        int src[8], dst[8];
        load_idx8(ei, (size_t)base, src);
        load_idx8(ei, (size_t)EE + base, dst);
#pragma unroll
        for (int j = 0; j < 8; j++) {
            int pos = atomicAdd(&d_cursor[dst[j]], 1);
            d_csr[pos] = make_int2(src[j],
                                   __float_as_int(d_dinv[src[j]] * d_dinv[dst[j]]));
        }
    }
}

// pack + transpose weights to fp16
__global__ void k_pack2(const float* __restrict__ W1,
                        const float* __restrict__ Wmu, const float* __restrict__ Wls,
                        const float* __restrict__ bmu, const float* __restrict__ bls) {
    int idx = blockIdx.x * 256 + threadIdx.x;
    if (idx < 65536) {
        int n = idx >> 8, k = idx & 255;
        d_W1Tf16[idx] = __float2half_rn(W1[k * 256 + n]);
        float bc = (n < OUTC) ? Wmu[k * OUTC + n] : Wls[k * OUTC + (n - OUTC)];
        d_BcTf16[idx] = __float2half_rn(bc);
    }
    if (idx < 256) d_bcat[idx] = (idx < OUTC) ? bmu[idx] : bls[idx - OUTC];
}

// ---------------- aggregation (fp16 gather via CSR, fp32 accumulate) ----------
// BUF=0: d_h0f16 -> d_hf16 (relu+bias). BUF=1: d_hf16 -> d_gf16.
template <int BUF>
__global__ __launch_bounds__(256) void k_agg(const float* __restrict__ bias) {
    int node = blockIdx.x * 8 + threadIdx.y;
    if (node >= NN) return;
    int lane = threadIdx.x;  // handles features [lane*8, lane*8+8)
    const uint4* sf = (BUF == 0) ? (const uint4*)d_h0f16 : (const uint4*)d_hf16;

    float di = d_dinv[node];
    float w0 = di * di;
    float acc[8];
    {
        uint4 v = sf[(size_t)node * 32 + lane];
        __half2* h = (__half2*)&v;
#pragma unroll
        for (int i = 0; i < 4; i++) {
            float2 f = __half22float2(h[i]);
            acc[2 * i]     = w0 * f.x;
            acc[2 * i + 1] = w0 * f.y;
        }
    }

    int beg = d_rowptr[node], end = d_rowptr[node + 1];
    int e = beg;
    for (; e + 8 <= end; e += 8) {
        int2 c[8];
        uint4 v[8];
#pragma unroll
        for (int j = 0; j < 8; j++) c[j] = d_csr[e + j];
#pragma unroll
        for (int j = 0; j < 8; j++) v[j] = sf[(size_t)c[j].x * 32 + lane];
#pragma unroll
        for (int j = 0; j < 8; j++) fma8(acc, v[j], __int_as_float(c[j].y));
    }
    for (; e + 2 <= end; e += 2) {
        int2 c0 = d_csr[e], c1 = d_csr[e + 1];
        uint4 v0 = sf[(size_t)c0.x * 32 + lane];
        uint4 v1 = sf[(size_t)c1.x * 32 + lane];
        fma8(acc, v0, __int_as_float(c0.y));
        fma8(acc, v1, __int_as_float(c1.y));
    }
    if (e < end) {
        int2 c = d_csr[e];
        uint4 v = sf[(size_t)c.x * 32 + lane];
        fma8(acc, v, __int_as_float(c.y));
    }

    uint4 outv;
    __half2* oh = (__half2*)&outv;
    if (BUF == 0) {
        const float4* b4 = (const float4*)bias;
        float4 ba = b4[lane * 2];
        float4 bb = b4[lane * 2 + 1];
        float bv[8] = {ba.x, ba.y, ba.z, ba.w, bb.x, bb.y, bb.z, bb.w};
#pragma unroll
        for (int i = 0; i < 4; i++) {
            float fx = fmaxf(acc[2 * i]     + bv[2 * i],     0.f);
            float fy = fmaxf(acc[2 * i + 1] + bv[2 * i + 1], 0.f);
            oh[i] = __floats2half2_rn(fx, fy);
        }
        ((uint4*)d_hf16)[(size_t)node * 32 + lane] = outv;
    } else {
#pragma unroll
        for (int i = 0; i < 4; i++)
            oh[i] = __floats2half2_rn(acc[2 * i], acc[2 * i + 1]);
        ((uint4*)d_gf16)[(size_t)node * 32 + lane] = outv;
    }
}

// ---------------- mma.sync fp16 GEMM, 512 threads, full N=256 per block -------
#define TILE_A 16384   // 128 rows x 128B (64 fp16)
#define TILE_BB 32768  // 256 rows x 128B
#define GSMEM  (TILE_A + TILE_BB)

__device__ __forceinline__ void load_tileA_h(char* tile, const __half* __restrict__ src,
                                             int row0, int nvalid, int col0) {
    int t = threadIdx.x;
    int r = t >> 2;
    int qb = (t & 3) * 32;
    const char* srow = (const char*)(src + (size_t)(row0 + r) * 256 + col0);
    bool valid = r < nvalid;
#pragma unroll
    for (int i = 0; i < 2; i++) {
        int b = qb + i * 16;
        uint4 v = valid ? *(const uint4*)(srow + b) : make_uint4(0u, 0u, 0u, 0u);
        uint32_t off = (uint32_t)(r * 128 + b);
        off ^= ((off >> 3) & 0x70);
        *(uint4*)(tile + off) = v;
    }
}
__device__ __forceinline__ void load_tileA_cvt(char* tile, const float* __restrict__ src,
                                               int row0, int nvalid, int col0) {
    int t = threadIdx.x;
    int r = t >> 2;
    int qf = (t & 3) * 16;
    const float* srow = src + (size_t)(row0 + r) * 256 + col0 + qf;
    bool valid = r < nvalid;
#pragma unroll
    for (int i = 0; i < 2; i++) {
        float4 f0 = valid ? *(const float4*)(srow + i * 8)     : make_float4(0.f, 0.f, 0.f, 0.f);
        float4 f1 = valid ? *(const float4*)(srow + i * 8 + 4) : make_float4(0.f, 0.f, 0.f, 0.f);
        uint4 hv;
        __half2* h = (__half2*)&hv;
        h[0] = __floats2half2_rn(f0.x, f0.y);
        h[1] = __floats2half2_rn(f0.z, f0.w);
        h[2] = __floats2half2_rn(f1.x, f1.y);
        h[3] = __floats2half2_rn(f1.z, f1.w);
        uint32_t off = (uint32_t)(r * 128 + qf * 2 + i * 16);
        off ^= ((off >> 3) & 0x70);
        *(uint4*)(tile + off) = hv;
    }
}
__device__ __forceinline__ void load_tileB_h(char* tile, const __half* __restrict__ src,
                                             int col0) {
    int t = threadIdx.x;
    int r = t >> 1;
    int hb = (t & 1) * 64;
    const char* srow = (const char*)(src + (size_t)r * 256 + col0);
#pragma unroll
    for (int i = 0; i < 4; i++) {
        int b = hb + i * 16;
        uint4 v = *(const uint4*)(srow + b);
        uint32_t off = (uint32_t)(r * 128 + b);
        off ^= ((off >> 3) & 0x70);
        *(uint4*)(tile + off) = v;
    }
}

template <int MODE>
__global__ __launch_bounds__(512) void k_gemm_mma(const float* __restrict__ Ax,
                                                  float* __restrict__ Cp) {
    extern __shared__ char smem[];
    char* sA = smem;
    char* sB = smem + TILE_A;
    uint32_t bA = smem_u32(sA), bB = bA + TILE_A;

    int tid = threadIdx.x, wid = tid >> 5, lane = tid & 31;
    int wm = wid & 3, wn = wid >> 2;
    int bm = blockIdx.x * 128;

    const __half* B = (MODE == 0) ? d_W1Tf16 : d_BcTf16;

    int navalid = NN - bm; if (navalid > 128) navalid = 128;

    float acc[2][8][4];
#pragma unroll
    for (int i = 0; i < 2; i++)
#pragma unroll
        for (int j = 0; j < 8; j++)
#pragma unroll
            for (int q = 0; q < 4; q++) acc[i][j][q] = 0.f;

    int a_row_off = ((lane >> 3) & 1) * 8 + (lane & 7);
    int a_kc_off  = (lane >> 4);
    int b_row_off = (lane >> 4) * 8 + (lane & 7);
    int b_kc_off  = ((lane >> 3) & 1);

    for (int c = 0; c < 4; c++) {
        if (c > 0) __syncthreads();
        if (MODE == 0) load_tileA_cvt(sA, Ax, bm, navalid, c * 64);
        else           load_tileA_h(sA, d_gf16, bm, navalid, c * 64);
        load_tileB_h(sB, B, c * 64);
        __syncthreads();

#pragma unroll
        for (int ks = 0; ks < 4; ks++) {
            int kc0 = ks * 2;
            uint32_t a[2][4];
#pragma unroll
            for (int mi = 0; mi < 2; mi++) {
                int row = wm * 32 + mi * 16 + a_row_off;
                ldmat_x4(a[mi][0], a[mi][1], a[mi][2], a[mi][3],
                         sw_addr(bA, row, kc0 + a_kc_off));
            }
#pragma unroll
            for (int ng = 0; ng < 4; ng++) {
                int nrow = wn * 64 + ng * 16 + b_row_off;
                uint32_t b[4];
                ldmat_x4(b[0], b[1], b[2], b[3], sw_addr(bB, nrow, kc0 + b_kc_off));
#pragma unroll
                for (int mi = 0; mi < 2; mi++) {
                    mma_f16(acc[mi][ng * 2],     a[mi], b[0], b[1]);
                    mma_f16(acc[mi][ng * 2 + 1], a[mi], b[2], b[3]);
                }
            }
        }
    }

#pragma unroll
    for (int mi = 0; mi < 2; mi++) {
        int r0 = bm + wm * 32 + mi * 16 + (lane >> 2);
#pragma unroll
        for (int ni = 0; ni < 8; ni++) {
            int ng = wn * 64 + ni * 8 + (lane & 3) * 2;  // global col 0..255
            float* a = acc[mi][ni];
            if (MODE == 0) {
                if (r0 < NN)
                    *(__half2*)&d_h0f16[(size_t)r0 * 256 + ng] =
                        __floats2half2_rn(a[0], a[1]);
                if (r0 + 8 < NN)
                    *(__half2*)&d_h0f16[(size_t)(r0 + 8) * 256 + ng] =
                        __floats2half2_rn(a[2], a[3]);
            } else {
                float bx = d_bcat[ng], by = d_bcat[ng + 1];
                size_t half_off = (ng < OUTC) ? 0 : (size_t)NN * OUTC;
                int ocol = ng & (OUTC - 1);
                if (r0 < NN)
                    *(float2*)&Cp[half_off + (size_t)r0 * OUTC + ocol] =
                        make_float2(a[0] + bx, a[1] + by);
                if (r0 + 8 < NN)
                    *(float2*)&Cp[half_off + (size_t)(r0 + 8) * OUTC + ocol] =
                        make_float2(a[2] + bx, a[3] + by);
            }
        }
    }
}

// ---------------- launch ----------------
extern "C" void kernel_launch(void* const* d_in, const int* in_sizes, int n_in,
                              void* d_out, int out_size) {
    const float* x   = (const float*)d_in[0];
    const void*  ei  = d_in[1];
    const float* W1  = (const float*)d_in[2];
    const float* b1  = (const float*)d_in[3];
    const float* Wmu = (const float*)d_in[4];
    const float* bmu = (const float*)d_in[5];
    const float* Wls = (const float*)d_in[6];
    const float* bls = (const float*)d_in[7];
    float* out = (float*)d_out;

    cudaFuncSetAttribute(k_gemm_mma<0>, cudaFuncAttributeMaxDynamicSharedMemorySize, GSMEM);
    cudaFuncSetAttribute(k_gemm_mma<1>, cudaFuncAttributeMaxDynamicSharedMemorySize, GSMEM);

    void* p_deg = nullptr;
    cudaGetSymbolAddress(&p_deg, d_deg);

    dim3 ggrid((NN + 127) / 128);
    dim3 agrid((NN + 7) / 8);
    dim3 ablk(32, 8);

    cudaStream_t s1;
    cudaStreamCreateWithFlags(&s1, cudaStreamNonBlocking);
    cudaEvent_t e0, eG0;
    cudaEventCreateWithFlags(&e0,  cudaEventDisableTiming);
    cudaEventCreateWithFlags(&eG0, cudaEventDisableTiming);

    cudaEventRecord(e0, 0);
    cudaStreamWaitEvent(s1, e0, 0);

    // branch B (s1): pack weights, then GEMM0 (x @ W1 -> d_h0f16)
    k_pack2<<<(65536 + 255) / 256, 256, 0, s1>>>(W1, Wmu, Wls, bmu, bls);
    k_gemm_mma<0><<<ggrid, 512, GSMEM, s1>>>(x, nullptr);
    cudaEventRecord(eG0, s1);

    // branch A (stream 0): CSR build
    cudaMemsetAsync(p_deg, 0, NN * sizeof(int), 0);
    k_detect<<<1, 32>>>((const unsigned long long*)ei);
    k_count<<<(EE / 8 + 255) / 256, 256>>>(ei);
    k_scan1<<<NB_S, 512>>>();
    k_scan3<<<NB_S, 512>>>();
    k_fill<<<(EE / 8 + 255) / 256, 256>>>(ei);

    // join: agg0 needs d_h0f16 + CSR
    cudaStreamWaitEvent(0, eG0, 0);
    k_agg<0><<<agrid, ablk>>>(b1);
    k_agg<1><<<agrid, ablk>>>(nullptr);
    k_gemm_mma<1><<<ggrid, 512, GSMEM>>>(nullptr, out);
}